// round 17
// baseline (speedup 1.0000x reference)
#include <cuda_runtime.h>
#include <cuda_bf16.h>
#include <cstdint>

#define DMODEL  4096
#define NEXP    64
#define TPB     64                  // tokens per CTA
#define KC      32                  // K per tile
#define NIT     (DMODEL / KC)       // 128 tiles
#define THREADS 512

#define XROW  36
#define WROW  72
#define XST   (64 * XROW * 4)       // 9216 B per stage
#define WST   (32 * WROW * 4)       // 9216 B per stage
#define OFF_XS 0
#define OFF_WS (2 * XST)            // 18432
#define OFF_BIAS (OFF_WS + 2 * WST) // 36864
#define SM_BYTES (OFF_BIAS + 256)   // 37120

__device__ __forceinline__ uint32_t smem_u32(const void* p) {
    uint32_t a;
    asm("{ .reg .u64 t; cvta.to.shared.u64 t, %1; cvt.u32.u64 %0, t; }" : "=r"(a) : "l"(p));
    return a;
}
__device__ __forceinline__ void cp16(uint32_t dst, const void* src) {
    asm volatile("cp.async.cg.shared.global [%0], [%1], 16;" :: "r"(dst), "l"(src));
}
__device__ __forceinline__ void cp_commit() { asm volatile("cp.async.commit_group;" ::: "memory"); }
__device__ __forceinline__ void cp_wait0()  { asm volatile("cp.async.wait_group 0;" ::: "memory"); }

__global__ __launch_bounds__(THREADS, 2) void router_kernel(
    const float* __restrict__ x, const float* __restrict__ W,
    const float* __restrict__ b,
    float* __restrict__ probs_out, float* __restrict__ tkp_out,
    float* __restrict__ tki_out)
{
    __shared__ __align__(16) char sAll[SM_BYTES];
    const uint32_t sb = smem_u32(sAll);

    const int tid  = threadIdx.x;
    const int w    = tid >> 5;
    const int lane = tid & 31;
    // warp spans 16 experts x 16 tokens -> warp-distinct smem bytes unchanged
    const int e0   = (w & 3) * 16 + (lane & 3) * 4;      // 4 experts
    const int t0   = (w >> 2) * 16 + (lane >> 2) * 2;    // 2 tokens
    const int tok0 = blockIdx.x * TPB;

    if (tid < NEXP) *(float*)(sAll + OFF_BIAS + tid * 4) = b[tid];

    // cp.async maps: X 512 chunks, W 512 chunks -> exactly 1 each per thread
    const int xrow = tid >> 3, xcol = tid & 7;          // X: [64][8] float4
    const int wrow = tid >> 4, wcol = tid & 15;         // W: [32][16] float4

    auto issue_cp = [&](int st, int k0) {
        cp16(sb + OFF_XS + st * XST + xrow * 144 + xcol * 16,
             &x[(size_t)(tok0 + xrow) * DMODEL + k0 + xcol * 4]);
        cp16(sb + OFF_WS + st * WST + wrow * 288 + wcol * 16,
             &W[(size_t)(k0 + wrow) * NEXP + wcol * 4]);
        cp_commit();
    };

    float acc[2][4];
    #pragma unroll
    for (int i = 0; i < 2; i++)
        #pragma unroll
        for (int j = 0; j < 4; j++) acc[i][j] = 0.f;

    // ---- prologue ----
    issue_cp(0, 0);

    // ---- mainloop ----
    #pragma unroll 1
    for (int it = 0; it < NIT; it++) {
        const int s = it & 1;
        cp_wait0();
        __syncthreads();                 // stage s landed; stage s^1 free

        if (it + 1 < NIT) issue_cp(s ^ 1, (it + 1) * KC);

        const float* xs = (const float*)(sAll + OFF_XS + s * XST);
        const float* ws = (const float*)(sAll + OFF_WS + s * WST);

        #pragma unroll
        for (int kg = 0; kg < KC / 4; kg++) {
            float4 xv0 = *(const float4*)&xs[t0 * XROW + kg * 4];
            float4 xv1 = *(const float4*)&xs[(t0 + 1) * XROW + kg * 4];
            #pragma unroll
            for (int kc = 0; kc < 4; kc++) {
                float4 wv = *(const float4*)&ws[(kg * 4 + kc) * WROW + e0];
                const float x0 = kc == 0 ? xv0.x : kc == 1 ? xv0.y : kc == 2 ? xv0.z : xv0.w;
                const float x1 = kc == 0 ? xv1.x : kc == 1 ? xv1.y : kc == 2 ? xv1.z : xv1.w;
                acc[0][0] = fmaf(x0, wv.x, acc[0][0]);
                acc[0][1] = fmaf(x0, wv.y, acc[0][1]);
                acc[0][2] = fmaf(x0, wv.z, acc[0][2]);
                acc[0][3] = fmaf(x0, wv.w, acc[0][3]);
                acc[1][0] = fmaf(x1, wv.x, acc[1][0]);
                acc[1][1] = fmaf(x1, wv.y, acc[1][1]);
                acc[1][2] = fmaf(x1, wv.z, acc[1][2]);
                acc[1][3] = fmaf(x1, wv.w, acc[1][3]);
            }
        }
    }

    // ---- epilogue: dump logits to smem (stride 68), per-token softmax/top-2 ----
    __syncthreads();
    {
        float* sf = (float*)sAll;
        *(float4*)&sf[t0 * 68 + e0]       = make_float4(acc[0][0], acc[0][1], acc[0][2], acc[0][3]);
        *(float4*)&sf[(t0 + 1) * 68 + e0] = make_float4(acc[1][0], acc[1][1], acc[1][2], acc[1][3]);
    }
    __syncthreads();

    if (tid < TPB) {
        const float* sf = (const float*)sAll;
        const float* sbias = (const float*)(sAll + OFF_BIAS);
        float p[64];
        #pragma unroll
        for (int c = 0; c < 64; c++)
            p[c] = sf[tid * 68 + c] + sbias[c];

        float m = p[0];
        #pragma unroll
        for (int c = 1; c < 64; c++) m = fmaxf(m, p[c]);
        float sum = 0.f;
        #pragma unroll
        for (int c = 0; c < 64; c++) { p[c] = __expf(p[c] - m); sum += p[c]; }
        const float inv = 1.f / sum;
        #pragma unroll
        for (int c = 0; c < 64; c++) p[c] *= inv;

        #pragma unroll
        for (int c4 = 0; c4 < 16; c4++)
            *(float4*)&probs_out[(size_t)(tok0 + tid) * NEXP + c4 * 4] =
                make_float4(p[c4 * 4], p[c4 * 4 + 1], p[c4 * 4 + 2], p[c4 * 4 + 3]);

        float p1 = -1.f, p2 = -1.f;
        int e1 = 0, e2 = 0;
        #pragma unroll
        for (int c = 0; c < 64; c++) {
            float pv = p[c];
            if (pv > p1)      { p2 = p1; e2 = e1; p1 = pv; e1 = c; }
            else if (pv > p2) { p2 = pv; e2 = c; }
        }

        const int token = tok0 + tid;
        const float is2 = 1.f / (p1 + p2 + 1e-9f);
        *(float2*)&tkp_out[(size_t)token * 2] = make_float2(p1 * is2, p2 * is2);
        *(float2*)&tki_out[(size_t)token * 2] = make_float2((float)e1, (float)e2);
    }
}

extern "C" void kernel_launch(void* const* d_in, const int* in_sizes, int n_in,
                              void* d_out, int out_size) {
    const float* x = (const float*)d_in[0];   // [4,4096,4096]
    const float* W = (const float*)d_in[1];   // [4096,64]
    const float* b = (const float*)d_in[2];   // [64]

    const int n_tokens = in_sizes[0] / DMODEL;        // 16384
    float* probs = (float*)d_out;
    float* tkp   = probs + (size_t)n_tokens * NEXP;
    float* tki   = tkp + (size_t)n_tokens * 2;

    router_kernel<<<n_tokens / TPB, THREADS>>>(x, W, b, probs, tkp, tki);
}